// round 12
// baseline (speedup 1.0000x reference)
#include <cuda_runtime.h>

#define BB 2
#define DD 64
#define HH 128
#define WW 128
#define NS (BB*DD)      // 128 slices
#define BPS 4           // blocks per slice
#define NBLK (NS*BPS)   // 512 blocks
#define NT 256
#define NWARP 8
#define OROWS 32        // owned rows per block
#define GR 10           // halo rows each side (cap=10 makes this exact)
#define SROWS (OROWS + 2*GR)   // 52 packed rows
#define SSTR 7          // words per packed row: [gL, W0..W3, gR, pad]; gcd(7,32)=1

constexpr int count_tab() {
    int n = 0;
    for (int dr = -9; dr <= 9; ++dr)
        for (int dc = -9; dc <= 9; ++dc) {
            int d2 = dr * dr + dc * dc;
            if (d2 >= 1 && d2 <= 99) ++n;
        }
    return n;
}
constexpr int TABN = count_tab();           // 304
constexpr int count_groups() {
    int n = 0;
    for (int d2 = 1; d2 <= 99; ++d2) {
        bool any = false;
        for (int dr = -9; dr <= 9 && !any; ++dr)
            for (int dc = -9; dc <= 9; ++dc)
                if (dr * dr + dc * dc == d2) { any = true; break; }
        if (any) ++n;
    }
    return n;
}
constexpr int NG = count_groups();

constexpr double csqrt_(double x) {
    double g = x > 1.0 ? x : 1.0;
    for (int i = 0; i < 60; ++i) g = 0.5 * (g + x / g);
    return g;
}
struct OffTab {
    signed char dr[TABN], dc[TABN];
    short gstart[NG], gcnt[NG];
    float sv[NG];
};
constexpr OffTab make_tab() {
    OffTab t{};
    int n = 0, gi = 0;
    for (int d2 = 1; d2 <= 99; ++d2) {
        int start = n;
        for (int dr = -9; dr <= 9; ++dr)
            for (int dc = -9; dc <= 9; ++dc)
                if (dr * dr + dc * dc == d2) {
                    t.dr[n] = (signed char)dr; t.dc[n] = (signed char)dc; ++n;
                }
        if (n > start) {
            t.gstart[gi] = (short)start;
            t.gcnt[gi]   = (short)(n - start);
            t.sv[gi]     = (float)csqrt_((double)d2);
            ++gi;
        }
    }
    return t;
}
__device__ constexpr OffTab TB = make_tab();

__device__ volatile float g_part_sum[NBLK];
__device__ volatile float g_part_cnt[NBLK];
__device__ volatile int   g_part_fg[NBLK];
__device__ unsigned int   g_done = 0;

// compress 8 nibbles (low 4 bits of each byte) into a 32-bit word,
// preserving pixel order: result bit (4j+i) = bit i of byte j.
__device__ __forceinline__ unsigned nib_compress(unsigned long long x) {
    x = (x | (x >> 4))  & 0x00FF00FF00FF00FFull;
    x = (x | (x >> 8))  & 0x0000FFFF0000FFFFull;
    x = (x | (x >> 16));
    return (unsigned)x;
}

// Templated walk: W (word index 0..3) compile-time -> valid masks and word
// offsets fold to immediates. Batches of 4 d2-groups for gi<8 (exit unlikely
// there), then per-group exit tests. found seeded with ~y_true; unfound
// pixels contribute exactly the clamp value 10.
template<int W>
__device__ __forceinline__ float walk(const unsigned* __restrict__ rowbase,
                                      const unsigned self, unsigned found,
                                      const int gr)
{
    float sum = 0.0f;
    #pragma unroll
    for (int bi = 0; bi < 2; ++bi) {
        unsigned gorv[4] = {0u, 0u, 0u, 0u};
        #pragma unroll
        for (int q = 0; q < 4; ++q) {
            const int gi = bi * 4 + q;
            #pragma unroll
            for (int k = 0; k < TB.gcnt[gi]; ++k) {
                const int dr = (int)TB.dr[TB.gstart[gi] + k];
                const int dc = (int)TB.dc[TB.gstart[gi] + k];
                const unsigned* rw = rowbase + dr * SSTR;
                unsigned sh, valid;
                if (dc >= 0) {
                    sh = __funnelshift_r(rw[1 + W], rw[2 + W], dc);
                    valid = (W == 3) ? (0xffffffffu >> dc) : 0xffffffffu;
                } else {
                    const int kk = -dc;
                    sh = __funnelshift_l(rw[W], rw[1 + W], kk);
                    valid = (W == 0) ? (0xffffffffu << kk) : 0xffffffffu;
                }
                unsigned rv = ((unsigned)(gr + dr) < (unsigned)HH) ? 0xffffffffu : 0u;
                gorv[q] |= (self ^ sh) & valid & rv;
            }
        }
        #pragma unroll
        for (int q = 0; q < 4; ++q) {
            unsigned nw = gorv[q] & ~found;          // fresh-per-group exact:
            sum += TB.sv[bi * 4 + q] * (float)__popc(nw); // found absorbs earlier
            found |= nw;
        }
        if (found == 0xffffffffu) return sum;
    }
    #pragma unroll
    for (int gi = 8; gi < NG; ++gi) {
        unsigned gor = 0u;
        #pragma unroll
        for (int k = 0; k < TB.gcnt[gi]; ++k) {
            const int dr = (int)TB.dr[TB.gstart[gi] + k];
            const int dc = (int)TB.dc[TB.gstart[gi] + k];
            const unsigned* rw = rowbase + dr * SSTR;
            unsigned sh, valid;
            if (dc >= 0) {
                sh = __funnelshift_r(rw[1 + W], rw[2 + W], dc);
                valid = (W == 3) ? (0xffffffffu >> dc) : 0xffffffffu;
            } else {
                const int kk = -dc;
                sh = __funnelshift_l(rw[W], rw[1 + W], kk);
                valid = (W == 0) ? (0xffffffffu << kk) : 0xffffffffu;
            }
            unsigned rv = ((unsigned)(gr + dr) < (unsigned)HH) ? 0xffffffffu : 0u;
            gor |= (self ^ sh) & valid & rv;
        }
        unsigned nw = gor & ~found;
        sum += TB.sv[gi] * (float)__popc(nw);
        found |= nw;
        if (found == 0xffffffffu) return sum;
    }
    return sum + 10.0f * (float)__popc(~found);   // unfound => dist>=10 => clamp
}

// combined(px) = dist to nearest opposite-valued pixel (s binary => one EDT
// term always zero), clamped at 10. Bit-parallel: rows packed to 128-bit
// masks; per offset the opposite mask for 32 pixels is one xor of a funnel-
// shifted neighbor row. 4 blocks/slice (10-row packed halos, exact under the
// cap) for residency balance + cross-block pack/main overlap. Word-major main
// mapping makes W warp-uniform -> templated walk. Finalize fused via
// last-block atomic counter (self-resetting, graph-safe).
__global__ __launch_bounds__(NT)
void edt_kernel(const float* __restrict__ yp, const float* __restrict__ yt,
                float* __restrict__ out)
{
    __shared__ unsigned sS[SROWS][SSTR];
    __shared__ unsigned sY[OROWS][4];
    __shared__ unsigned char pS[SROWS][32];
    __shared__ unsigned char pY[OROWS][32];
    __shared__ float wsum[NWARP], wcnt[NWARP];
    __shared__ int s_islast;
    __shared__ unsigned s_fgw[4];
    __shared__ int s_first[BB], s_last[BB];

    const int blk   = blockIdx.x;
    const int slice = blk >> 2;
    const int R0    = (blk & 3) * OROWS;   // first owned global row
    const int t     = threadIdx.x;
    const int lane  = t & 31, wp = t >> 5;
    const float* yps = yp + (size_t)slice * HH * WW;
    const float* yts = yt + (size_t)slice * HH * WW;

    // zero packed array (covers guard words + out-of-range halo rows)
    for (int i = t; i < SROWS * SSTR; i += NT) ((unsigned*)sS)[i] = 0u;

    // ---- pack phase: MLP float4 loads, nibble per lane, no ballots ----
    #pragma unroll
    for (int it = 0; it < 7; ++it) {               // yp: 52 rows over 8 warps
        int rr = wp + it * NWARP;
        if (rr < SROWS) {
            int grow = R0 - GR + rr;
            float4 a = make_float4(0.f, 0.f, 0.f, 0.f);
            if ((unsigned)grow < (unsigned)HH)
                a = __ldg((const float4*)(yps + (size_t)grow * WW) + lane);
            unsigned n = (a.x > 0.7f ? 1u : 0u) | (a.y > 0.7f ? 2u : 0u)
                       | (a.z > 0.7f ? 4u : 0u) | (a.w > 0.7f ? 8u : 0u);
            pS[rr][lane] = (unsigned char)n;
        }
    }
    #pragma unroll
    for (int it = 0; it < 4; ++it) {               // yt: 32 owned rows
        int rr = wp + it * NWARP;
        float4 a = __ldg((const float4*)(yts + (size_t)(R0 + rr) * WW) + lane);
        unsigned n = (a.x != 0.0f ? 1u : 0u) | (a.y != 0.0f ? 2u : 0u)
                   | (a.z != 0.0f ? 4u : 0u) | (a.w != 0.0f ? 8u : 0u);
        pY[rr][lane] = (unsigned char)n;
    }
    __syncthreads();

    // ---- assemble: u64 nibble-compress ----
    if (t < SROWS * 4) {
        int rr = t >> 2, w = t & 3;
        sS[rr][1 + w] = nib_compress(*(const unsigned long long*)&pS[rr][w * 8]);
    }
    if (t < OROWS * 4) {
        int rr = t >> 2, w = t & 3;
        sY[rr][w] = nib_compress(*(const unsigned long long*)&pY[rr][w * 8]);
    }
    __syncthreads();

    // ---- main phase: threads 0..127, word-major (W warp-uniform) ----
    float sum = 0.0f, cntf = 0.0f;
    int fgflag = 0;
    if (t < OROWS * 4) {
        const int r = t & 31;              // local row
        const int W = t >> 5;              // word index, uniform per warp
        const int gr = R0 + r;
        const unsigned self = sS[GR + r][1 + W];
        const unsigned ytm  = sY[r][W];
        const unsigned* rowbase = &sS[GR + r][0];
        fgflag = (self != 0u);
        switch (W) {
            case 0: sum = walk<0>(rowbase, self, ~ytm, gr); break;
            case 1: sum = walk<1>(rowbase, self, ~ytm, gr); break;
            case 2: sum = walk<2>(rowbase, self, ~ytm, gr); break;
            default: sum = walk<3>(rowbase, self, ~ytm, gr); break;
        }
        cntf = (float)__popc(ytm);
    }
    int anyfg = __syncthreads_or(fgflag);

    // ---- block reduction (8 warps; idle lanes contribute zeros) ----
    #pragma unroll
    for (int o = 16; o > 0; o >>= 1) {
        sum  += __shfl_down_sync(0xffffffffu, sum,  o);
        cntf += __shfl_down_sync(0xffffffffu, cntf, o);
    }
    if (lane == 0) { wsum[wp] = sum; wcnt[wp] = cntf; }
    __syncthreads();
    if (t == 0) {
        float s = 0.0f, c = 0.0f;
        #pragma unroll
        for (int i = 0; i < NWARP; i++) { s += wsum[i]; c += wcnt[i]; }
        g_part_sum[blk] = s;
        g_part_cnt[blk] = c;
        g_part_fg[blk]  = anyfg;
        __threadfence();
        unsigned old = atomicAdd(&g_done, 1u);
        s_islast = (old == NBLK - 1u);
        if (s_islast) g_done = 0;   // self-reset for graph replay
    }
    __syncthreads();
    if (!s_islast) return;

    // ---- fused finalize (last block): per-batch fg range + masked sum ----
    __threadfence();
    int f = 0;
    if (t < NS) {
        #pragma unroll
        for (int q = 0; q < BPS; ++q) f |= g_part_fg[BPS * t + q];
    }
    unsigned bal = __ballot_sync(0xffffffffu, f != 0);
    if (t < NS && lane == 0) s_fgw[wp] = bal;      // wp < 4 for t < 128
    __syncthreads();
    if (t < BB) {
        unsigned long long m = (unsigned long long)s_fgw[2 * t] |
                               ((unsigned long long)s_fgw[2 * t + 1] << 32);
        s_first[t] = m ? (__ffsll((long long)m) - 1) : 0;   // argmax(all-false)=0
        s_last[t]  = m ? (63 - __clzll((long long)m)) : (DD - 1);
    }
    __syncthreads();
    float ms = 0.0f, mc = 0.0f;
    #pragma unroll
    for (int q = 0; q < 2; ++q) {
        int p  = t + q * NT;               // part index (NBLK=512)
        int sl = p >> 2;
        int b  = sl >> 6, d = sl & (DD - 1);
        int in = (d >= s_first[b]) && (d <= s_last[b]);
        ms += in ? g_part_sum[p] : 0.0f;
        mc += g_part_cnt[p];
    }
    #pragma unroll
    for (int o = 16; o > 0; o >>= 1) {
        ms += __shfl_down_sync(0xffffffffu, ms, o);
        mc += __shfl_down_sync(0xffffffffu, mc, o);
    }
    if (lane == 0) { wsum[wp] = ms; wcnt[wp] = mc; }
    __syncthreads();
    if (t == 0) {
        float s = 0.0f, c = 0.0f;
        #pragma unroll
        for (int i = 0; i < NWARP; i++) { s += wsum[i]; c += wcnt[i]; }
        out[0] = s / c;
    }
}

extern "C" void kernel_launch(void* const* d_in, const int* in_sizes, int n_in,
                              void* d_out, int out_size)
{
    const float* yp = (const float*)d_in[0];
    const float* yt = (const float*)d_in[1];
    float* out = (float*)d_out;
    edt_kernel<<<NBLK, NT>>>(yp, yt, out);
}

// round 13
// speedup vs baseline: 1.0644x; 1.0644x over previous
#include <cuda_runtime.h>

#define BB 2
#define DD 64
#define HH 128
#define WW 128
#define NS (BB*DD)      // 128 slices
#define BPS 2           // blocks per slice
#define NBLK (NS*BPS)   // 256 blocks
#define NT 256
#define NWARP 8
#define OROWS 64        // owned rows per block
#define GR 10           // halo rows each side (cap=10 makes this exact)
#define SROWS (OROWS + 2*GR)   // 84 packed rows
#define SSTR 6          // words per packed row: [guard, W0..W3, guard]

constexpr int count_tab() {
    int n = 0;
    for (int dr = -9; dr <= 9; ++dr)
        for (int dc = -9; dc <= 9; ++dc) {
            int d2 = dr * dr + dc * dc;
            if (d2 >= 1 && d2 <= 99) ++n;
        }
    return n;
}
constexpr int TABN = count_tab();           // 304
constexpr int count_groups() {
    int n = 0;
    for (int d2 = 1; d2 <= 99; ++d2) {
        bool any = false;
        for (int dr = -9; dr <= 9 && !any; ++dr)
            for (int dc = -9; dc <= 9; ++dc)
                if (dr * dr + dc * dc == d2) { any = true; break; }
        if (any) ++n;
    }
    return n;
}
constexpr int NG = count_groups();
constexpr int NBATCH = (NG + 3) / 4;

constexpr double csqrt_(double x) {
    double g = x > 1.0 ? x : 1.0;
    for (int i = 0; i < 60; ++i) g = 0.5 * (g + x / g);
    return g;
}
struct OffTab {
    signed char dr[TABN], dc[TABN];
    short gstart[NG], gcnt[NG];
    float sv[NG];
};
constexpr OffTab make_tab() {
    OffTab t{};
    int n = 0, gi = 0;
    for (int d2 = 1; d2 <= 99; ++d2) {
        int start = n;
        for (int dr = -9; dr <= 9; ++dr)
            for (int dc = -9; dc <= 9; ++dc)
                if (dr * dr + dc * dc == d2) {
                    t.dr[n] = (signed char)dr; t.dc[n] = (signed char)dc; ++n;
                }
        if (n > start) {
            t.gstart[gi] = (short)start;
            t.gcnt[gi]   = (short)(n - start);
            t.sv[gi]     = (float)csqrt_((double)d2);
            ++gi;
        }
    }
    return t;
}
__device__ constexpr OffTab TB = make_tab();

__device__ volatile float g_part_sum[NBLK];
__device__ volatile float g_part_cnt[NBLK];
__device__ volatile int   g_part_fg[NBLK];
__device__ unsigned int   g_done = 0;

// compress 8 nibbles (low 4 bits of each byte) into a 32-bit word,
// preserving pixel order: result bit (4j+i) = bit i of byte j.
__device__ __forceinline__ unsigned nib_compress(unsigned long long x) {
    x = (x | (x >> 4))  & 0x00FF00FF00FF00FFull;
    x = (x | (x >> 8))  & 0x0000FFFF0000FFFFull;
    x = (x | (x >> 16));
    return (unsigned)x;
}

// Offset walk: fully unrolled (compile-time dr/dc -> immediate shifts, CSE'd
// row loads), batches of 4 d2-groups with independent accumulators, one exit
// test per batch. BND=false (rows with full 9-row vertical margin) drops the
// row-validity mask. found seeded with ~y_true; unfound pixels contribute
// exactly the clamp value 10.
template<bool BND>
__device__ __forceinline__ float walk(const unsigned* __restrict__ rowbase,
                                      const unsigned self, unsigned found,
                                      const int gr, const int w)
{
    float sum = 0.0f;
    #pragma unroll
    for (int bi = 0; bi < NBATCH; ++bi) {
        unsigned gorv[4] = {0u, 0u, 0u, 0u};
        #pragma unroll
        for (int q = 0; q < 4; ++q) {
            const int gi = bi * 4 + q;
            if (gi < NG) {
                #pragma unroll
                for (int k = 0; k < TB.gcnt[gi]; ++k) {
                    const int dr = (int)TB.dr[TB.gstart[gi] + k];
                    const int dc = (int)TB.dc[TB.gstart[gi] + k];
                    const unsigned* rw = rowbase + dr * SSTR;
                    unsigned sh, valid;
                    if (dc >= 0) {
                        sh = __funnelshift_r(rw[1 + w], rw[2 + w], dc);
                        valid = (w == 3) ? (0xffffffffu >> dc) : 0xffffffffu;
                    } else {
                        const int kk = -dc;
                        sh = __funnelshift_l(rw[w], rw[1 + w], kk);
                        valid = (w == 0) ? (0xffffffffu << kk) : 0xffffffffu;
                    }
                    unsigned m = (self ^ sh) & valid;
                    if (BND) {
                        unsigned rv = ((unsigned)(gr + dr) < (unsigned)HH)
                                        ? 0xffffffffu : 0u;
                        m &= rv;
                    }
                    gorv[q] |= m;
                }
            }
        }
        #pragma unroll
        for (int q = 0; q < 4; ++q) {
            const int gi = bi * 4 + q;
            if (gi < NG) {
                unsigned nw = gorv[q] & ~found;       // fresh-per-group exact:
                sum += TB.sv[gi] * (float)__popc(nw); // found absorbs earlier
                found |= nw;
            }
        }
        if (found == 0xffffffffu) return sum;
    }
    return sum + 10.0f * (float)__popc(~found);   // unfound => dist>=10 => clamp
}

// combined(px) = dist to nearest opposite-valued pixel (s binary => one EDT
// term always zero), clamped at 10. Bit-parallel: rows packed to 128-bit
// masks; per offset the opposite mask for 32 pixels is one xor of a funnel-
// shifted neighbor row. 2 blocks/slice (10-row packed halos, exact under the
// cap), 256 threads: ALL threads active in the walk, ~4 resident blocks/SM so
// one block's pack (DRAM) overlaps another's walk (ALU/LDS). Pack: MLP float4
// loads -> nibble staging -> u64 compress, no ballots. Finalize fused via
// last-block atomic counter (self-resetting, graph-safe).
__global__ __launch_bounds__(NT)
void edt_kernel(const float* __restrict__ yp, const float* __restrict__ yt,
                float* __restrict__ out)
{
    __shared__ unsigned sS[SROWS][SSTR];
    __shared__ unsigned sY[OROWS][4];
    __shared__ unsigned char pS[SROWS][32];
    __shared__ unsigned char pY[OROWS][32];
    __shared__ float wsum[NWARP], wcnt[NWARP];
    __shared__ int s_islast;
    __shared__ unsigned s_fgw[4];
    __shared__ int s_first[BB], s_last[BB];

    const int blk   = blockIdx.x;
    const int slice = blk >> 1;
    const int R0    = (blk & 1) * OROWS;   // first owned global row
    const int t     = threadIdx.x;
    const int lane  = t & 31, wp = t >> 5;
    const float* yps = yp + (size_t)slice * HH * WW;
    const float* yts = yt + (size_t)slice * HH * WW;

    // zero guard word columns of sS
    for (int i = t; i < SROWS * SSTR; i += NT) ((unsigned*)sS)[i] = 0u;

    // ---- pack phase: MLP float4 loads, nibble per lane, no ballots ----
    #pragma unroll
    for (int it = 0; it < 11; ++it) {              // yp: 84 rows over 8 warps
        int rr = wp + it * NWARP;
        if (rr < SROWS) {
            int grow = R0 - GR + rr;
            float4 a = make_float4(0.f, 0.f, 0.f, 0.f);
            if ((unsigned)grow < (unsigned)HH)
                a = __ldg((const float4*)(yps + (size_t)grow * WW) + lane);
            unsigned n = (a.x > 0.7f ? 1u : 0u) | (a.y > 0.7f ? 2u : 0u)
                       | (a.z > 0.7f ? 4u : 0u) | (a.w > 0.7f ? 8u : 0u);
            pS[rr][lane] = (unsigned char)n;
        }
    }
    #pragma unroll
    for (int it = 0; it < 8; ++it) {               // yt: 64 owned rows
        int rr = wp + it * NWARP;
        float4 a = __ldg((const float4*)(yts + (size_t)(R0 + rr) * WW) + lane);
        unsigned n = (a.x != 0.0f ? 1u : 0u) | (a.y != 0.0f ? 2u : 0u)
                   | (a.z != 0.0f ? 4u : 0u) | (a.w != 0.0f ? 8u : 0u);
        pY[rr][lane] = (unsigned char)n;
    }
    __syncthreads();

    // ---- assemble: u64 nibble-compress ----
    for (int i = t; i < SROWS * 4; i += NT) {
        int rr = i >> 2, w = i & 3;
        sS[rr][1 + w] = nib_compress(*(const unsigned long long*)&pS[rr][w * 8]);
    }
    {
        int rr = t >> 2, w = t & 3;                // 256 tasks exactly
        sY[rr][w] = nib_compress(*(const unsigned long long*)&pY[rr][w * 8]);
    }
    __syncthreads();

    // ---- main phase: thread <-> (owned row, word); all 256 threads busy ----
    const int r = t >> 2, w = t & 3;
    const int gr = R0 + r;
    const unsigned self = sS[GR + r][1 + w];
    const unsigned ytm  = sY[r][w];
    const unsigned* rowbase = &sS[GR + r][0];
    int fgflag = (self != 0u);
    float sum;
    if (gr >= 9 && gr <= HH - 10)
        sum = walk<false>(rowbase, self, ~ytm, gr, w);
    else
        sum = walk<true>(rowbase, self, ~ytm, gr, w);
    float cntf = (float)__popc(ytm);
    int anyfg = __syncthreads_or(fgflag);

    // ---- block reduction (8 warps) ----
    #pragma unroll
    for (int o = 16; o > 0; o >>= 1) {
        sum  += __shfl_down_sync(0xffffffffu, sum,  o);
        cntf += __shfl_down_sync(0xffffffffu, cntf, o);
    }
    if (lane == 0) { wsum[wp] = sum; wcnt[wp] = cntf; }
    __syncthreads();
    if (t == 0) {
        float s = 0.0f, c = 0.0f;
        #pragma unroll
        for (int i = 0; i < NWARP; i++) { s += wsum[i]; c += wcnt[i]; }
        g_part_sum[blk] = s;
        g_part_cnt[blk] = c;
        g_part_fg[blk]  = anyfg;
        __threadfence();
        unsigned old = atomicAdd(&g_done, 1u);
        s_islast = (old == NBLK - 1u);
        if (s_islast) g_done = 0;   // self-reset for graph replay
    }
    __syncthreads();
    if (!s_islast) return;

    // ---- fused finalize (last block): per-batch fg range + masked sum ----
    __threadfence();
    int f = (t < NS) ? (g_part_fg[2 * t] | g_part_fg[2 * t + 1]) : 0;
    unsigned bal = __ballot_sync(0xffffffffu, f != 0);
    if (t < NS && lane == 0) s_fgw[wp] = bal;      // wp < 4 for t < 128
    __syncthreads();
    if (t < BB) {
        unsigned long long m = (unsigned long long)s_fgw[2 * t] |
                               ((unsigned long long)s_fgw[2 * t + 1] << 32);
        s_first[t] = m ? (__ffsll((long long)m) - 1) : 0;   // argmax(all-false)=0
        s_last[t]  = m ? (63 - __clzll((long long)m)) : (DD - 1);
    }
    __syncthreads();
    float ms, mc;
    {
        int sl = t >> 1;                   // one part per thread (NBLK == NT)
        int b  = sl >> 6, d = sl & (DD - 1);
        int in = (d >= s_first[b]) && (d <= s_last[b]);
        ms = in ? g_part_sum[t] : 0.0f;
        mc = g_part_cnt[t];
    }
    #pragma unroll
    for (int o = 16; o > 0; o >>= 1) {
        ms += __shfl_down_sync(0xffffffffu, ms, o);
        mc += __shfl_down_sync(0xffffffffu, mc, o);
    }
    if (lane == 0) { wsum[wp] = ms; wcnt[wp] = mc; }
    __syncthreads();
    if (t == 0) {
        float s = 0.0f, c = 0.0f;
        #pragma unroll
        for (int i = 0; i < NWARP; i++) { s += wsum[i]; c += wcnt[i]; }
        out[0] = s / c;
    }
}

extern "C" void kernel_launch(void* const* d_in, const int* in_sizes, int n_in,
                              void* d_out, int out_size)
{
    const float* yp = (const float*)d_in[0];
    const float* yt = (const float*)d_in[1];
    float* out = (float*)d_out;
    edt_kernel<<<NBLK, NT>>>(yp, yt, out);
}